// round 14
// baseline (speedup 1.0000x reference)
#include <cuda_runtime.h>
#include <cuda_fp16.h>
#include <cstdint>

// Problem shape (fixed by the dataset)
constexpr int B = 8, C = 16, H = 512, W = 512;
constexpr int HW = H * W;            // 262144 = 2^18
constexpr int CHW = C * HW;
constexpr int NPIX = B * HW;         // 2,097,152
constexpr int NOUT = B * CHW;        // 33,554,432

// Split-plane fp16 scratch, 64 MiB total (R10 layout):
//   plane LO = channels 0..7  : pixel p at 16B offset p*16
//   plane HI = channels 8..15 : same indexing, +32 MiB
__device__ __half g_scratch[NOUT];
constexpr size_t HI_OFF_H2 = (size_t)NPIX * 4;   // half2 offset of HI plane

// ---------------------------------------------------------------------------
// 16-byte fp16 vector reduction (hard max RED width): 8 halves per request.
// 8 such requests/pixel = 128B payload / 16B = provably minimal; the splat
// runs at the ~1.82cyc/transaction LSU floor -> ~104us is the floor.
// ---------------------------------------------------------------------------
__device__ __forceinline__ void red_v4h2(__half2* p, __half2 a, __half2 b,
                                         __half2 c, __half2 d) {
    unsigned ra = *(unsigned*)&a, rb = *(unsigned*)&b;
    unsigned rc = *(unsigned*)&c, rd = *(unsigned*)&d;
    asm volatile("red.global.add.noftz.v4.f16x2 [%0], {%1, %2, %3, %4};"
                 :: "l"(p), "r"(ra), "r"(rb), "r"(rc), "r"(rd) : "memory");
}

// ---------------------------------------------------------------------------
// Inverse bilinear splat into split-plane scratch (R13 body, unchanged).
// ---------------------------------------------------------------------------
__global__ __launch_bounds__(256, 8)
void splat_kernel(const float* __restrict__ x,
                  const float2* __restrict__ grid) {
    int idx = blockIdx.x * 256 + threadIdx.x;

    int b  = idx >> 18;        // / HW
    int hw = idx & (HW - 1);   // % HW

    float2 g = __ldcs(grid + idx);   // single-use: evict-first

    float gi = fminf(fmaxf((g.x + 1.0f) * 0.5f * (float)H + 1.0f, 0.0f), (float)(H + 1));
    float gj = fminf(fmaxf((g.y + 1.0f) * 0.5f * (float)W + 1.0f, 0.0f), (float)(W + 1));

    int   fi  = (int)gi;            // gi >= 0 so trunc == floor
    int   fj  = (int)gj;
    float fri = gi - (float)fi;
    float frj = gj - (float)fj;

    float w00 = (1.0f - fri) * (1.0f - frj);
    float w01 = (1.0f - fri) * frj;
    float w10 = fri * (1.0f - frj);
    float w11 = fri * frj;

    int oi0 = fi - 1;
    int oj0 = fj - 1;
    bool i0 = (unsigned)oi0       < (unsigned)H;
    bool i1 = (unsigned)(oi0 + 1) < (unsigned)H;
    bool j0 = (unsigned)oj0       < (unsigned)W;
    bool j1 = (unsigned)(oj0 + 1) < (unsigned)W;

    // 16 channel values, coalesced per channel, streaming (single use)
    const float* xp = x + (size_t)b * CHW + hw;
    float v[C];
#pragma unroll
    for (int c = 0; c < C; c++) v[c] = __ldcs(xp + c * HW);

    // Plane pointers for corner (oi0, oj0); pixel stride = 4 half2 (16B).
    size_t p00 = (size_t)b * HW + (size_t)oi0 * W + oj0;
    __half2* l00 = (__half2*)g_scratch + p00 * 4;              // LO, (i0,j0)
    __half2* l10 = l00 + (size_t)W * 4;                        // LO, (i1,j0)
    __half2* h00 = (__half2*)g_scratch + HI_OFF_H2 + p00 * 4;  // HI: +32MB
    __half2* h10 = h00 + (size_t)W * 4;

#define PACK4(dst, wgt, half)                                                   \
    {                                                                           \
        _Pragma("unroll")                                                       \
        for (int j = 0; j < 4; j++)                                             \
            dst[j] = __floats2half2_rn(v[8*(half) + 2*j]     * (wgt),           \
                                       v[8*(half) + 2*j + 1] * (wgt));          \
    }

    if (j0) {   // corners (i0,j0)/(i1,j0): plane- and i-alternated issue
        __half2 a[4], c[4];
        if (i0) { PACK4(a, w00, 0); red_v4h2(l00, a[0], a[1], a[2], a[3]); }
        if (i1) { PACK4(c, w10, 0); red_v4h2(l10, c[0], c[1], c[2], c[3]); }
        if (i0) { PACK4(a, w00, 1); red_v4h2(h00, a[0], a[1], a[2], a[3]); }
        if (i1) { PACK4(c, w10, 1); red_v4h2(h10, c[0], c[1], c[2], c[3]); }
    }
    if (j1) {   // corners (i0,j1)/(i1,j1): next pixel = +4 half2 (16B)
        __half2 a[4], c[4];
        if (i0) { PACK4(a, w01, 0); red_v4h2(l00 + 4, a[0], a[1], a[2], a[3]); }
        if (i1) { PACK4(c, w11, 0); red_v4h2(l10 + 4, c[0], c[1], c[2], c[3]); }
        if (i0) { PACK4(a, w01, 1); red_v4h2(h00 + 4, a[0], a[1], a[2], a[3]); }
        if (i1) { PACK4(c, w11, 1); red_v4h2(h10 + 4, c[0], c[1], c[2], c[3]); }
    }
#undef PACK4
}

// ---------------------------------------------------------------------------
// Transpose split-plane fp16 scratch -> f32 out (B,C,H,W).
// Fine-grained: 128 threads / 256-pixel tile, 8 KiB smem, grid 8192.
// Up to 16 blocks/SM -> better wave balance + latency hiding; each thread
// does 4 x 16B loads then 8 x float4 stores.
// ---------------------------------------------------------------------------
__global__ __launch_bounds__(128)
void transpose_kernel(const __half2* __restrict__ s, float* __restrict__ out) {
    __shared__ __half2 sm[8][256];   // 8 KiB: sm[r][p] = ch (2r,2r+1), pixel p

    int base = blockIdx.x * 256;     // 256 | HW: block never straddles b
    int t = threadIdx.x;

    // Load phase: 128 threads x 2 pixels, two 16B reads (LO/HI plane) each.
#pragma unroll
    for (int q = 0; q < 2; q++) {
        int p = t + 128 * q;
        uint4 a  = __ldcs((const uint4*)(s + (size_t)(base + p) * 4));             // ch 0..7
        uint4 bq = __ldcs((const uint4*)(s + HI_OFF_H2 + (size_t)(base + p) * 4)); // ch 8..15
        sm[0][p] = *(__half2*)&a.x;  sm[1][p] = *(__half2*)&a.y;
        sm[2][p] = *(__half2*)&a.z;  sm[3][p] = *(__half2*)&a.w;
        sm[4][p] = *(__half2*)&bq.x; sm[5][p] = *(__half2*)&bq.y;
        sm[6][p] = *(__half2*)&bq.z; sm[7][p] = *(__half2*)&bq.w;
    }
    __syncthreads();

    int b  = base >> 18;
    int hw = base & (HW - 1);
    float* ob = out + (size_t)b * CHW + hw;

    // Store phase: sub 0 -> channel pairs 0..3, sub 1 -> pairs 4..7.
    int sub = t >> 6;                // 0 or 1
    int tt  = t & 63;                // pixel-quad index (64 quads = 256 px)

#pragma unroll
    for (int r2 = 0; r2 < 4; r2++) {
        int r = sub * 4 + r2;
        uint4 raw = *(const uint4*)&sm[r][4 * tt];  // 4 half2 of channel pair r
        float2 f0 = __half22float2(*(__half2*)&raw.x);
        float2 f1 = __half22float2(*(__half2*)&raw.y);
        float2 f2 = __half22float2(*(__half2*)&raw.z);
        float2 f3 = __half22float2(*(__half2*)&raw.w);
        float4 ve = make_float4(f0.x, f1.x, f2.x, f3.x);  // channel 2r
        float4 vo = make_float4(f0.y, f1.y, f2.y, f3.y);  // channel 2r+1
        __stcs((float4*)(ob + (size_t)(2*r)     * HW) + tt, ve);
        __stcs((float4*)(ob + (size_t)(2*r + 1) * HW) + tt, vo);
    }
}

extern "C" void kernel_launch(void* const* d_in, const int* in_sizes, int n_in,
                              void* d_out, int out_size) {
    const float*  x    = (const float*)d_in[0];
    const float2* grid = (const float2*)d_in[1];
    float*        out  = (float*)d_out;

    static __half* scratch_ptr = nullptr;
    if (!scratch_ptr) cudaGetSymbolAddress((void**)&scratch_ptr, g_scratch);

    // 1) zero the fp16 scratch (standalone pure-write pass, ~9 TB/s)
    cudaMemsetAsync(scratch_ptr, 0, (size_t)NOUT * sizeof(__half), 0);

    // 2) splat: 8 x 16B REDs per pixel (minimal transaction count)
    splat_kernel<<<NPIX / 256, 256>>>(x, grid);

    // 3) transpose split-plane scratch into f32 (B,C,H,W) output
    transpose_kernel<<<NPIX / 256, 128>>>((const __half2*)scratch_ptr, out);
}

// round 15
// speedup vs baseline: 1.0713x; 1.0713x over previous
#include <cuda_runtime.h>
#include <cuda_fp16.h>
#include <cstdint>

// Problem shape (fixed by the dataset)
constexpr int B = 8, C = 16, H = 512, W = 512;
constexpr int HW = H * W;            // 262144 = 2^18
constexpr int CHW = C * HW;
constexpr int NPIX = B * HW;         // 2,097,152
constexpr int NOUT = B * CHW;        // 33,554,432

constexpr int HALF_PIX = 4 * HW;     // pixels in one 4-batch group = 1,048,576

// Split-plane fp16 scratch, 64 MiB (R10 layout):
//   LO plane (ch 0..7):  uint4[p]           for global pixel p
//   HI plane (ch 8..15): uint4[NPIX + p]
// Zero at module load. K3 re-zeroes batches 0-3, K1 re-zeroes batches 4-7
// (before K2 splats into them) -> "scratch==0 on entry" holds every replay.
__device__ __half g_scratch[NOUT];
constexpr size_t HI_OFF_H2 = (size_t)NPIX * 4;   // half2 offset of HI plane

// ---------------------------------------------------------------------------
// 16-byte fp16 vector reduction (hard max RED width): 8 halves per request.
// ---------------------------------------------------------------------------
__device__ __forceinline__ void red_v4h2(__half2* p, __half2 a, __half2 b,
                                         __half2 c, __half2 d) {
    unsigned ra = *(unsigned*)&a, rb = *(unsigned*)&b;
    unsigned rc = *(unsigned*)&c, rd = *(unsigned*)&d;
    asm volatile("red.global.add.noftz.v4.f16x2 [%0], {%1, %2, %3, %4};"
                 :: "l"(p), "r"(ra), "r"(rb), "r"(rc), "r"(rd) : "memory");
}

// ---------------------------------------------------------------------------
// Role: splat one pixel (R13 body). idx = global pixel index (b*HW + hw).
// ---------------------------------------------------------------------------
__device__ __forceinline__ void splat_pixel(const float* __restrict__ x,
                                            const float2* __restrict__ grid,
                                            int idx) {
    int b  = idx >> 18;        // / HW
    int hw = idx & (HW - 1);   // % HW

    float2 g = __ldcs(grid + idx);   // single-use: evict-first

    float gi = fminf(fmaxf((g.x + 1.0f) * 0.5f * (float)H + 1.0f, 0.0f), (float)(H + 1));
    float gj = fminf(fmaxf((g.y + 1.0f) * 0.5f * (float)W + 1.0f, 0.0f), (float)(W + 1));

    int   fi  = (int)gi;            // gi >= 0 so trunc == floor
    int   fj  = (int)gj;
    float fri = gi - (float)fi;
    float frj = gj - (float)fj;

    float w00 = (1.0f - fri) * (1.0f - frj);
    float w01 = (1.0f - fri) * frj;
    float w10 = fri * (1.0f - frj);
    float w11 = fri * frj;

    int oi0 = fi - 1;
    int oj0 = fj - 1;
    bool i0 = (unsigned)oi0       < (unsigned)H;
    bool i1 = (unsigned)(oi0 + 1) < (unsigned)H;
    bool j0 = (unsigned)oj0       < (unsigned)W;
    bool j1 = (unsigned)(oj0 + 1) < (unsigned)W;

    const float* xp = x + (size_t)b * CHW + hw;
    float v[C];
#pragma unroll
    for (int c = 0; c < C; c++) v[c] = __ldcs(xp + c * HW);

    size_t p00 = (size_t)b * HW + (size_t)oi0 * W + oj0;
    __half2* l00 = (__half2*)g_scratch + p00 * 4;              // LO, (i0,j0)
    __half2* l10 = l00 + (size_t)W * 4;                        // LO, (i1,j0)
    __half2* h00 = (__half2*)g_scratch + HI_OFF_H2 + p00 * 4;  // HI: +32MB
    __half2* h10 = h00 + (size_t)W * 4;

#define PACK4(dst, wgt, half)                                                   \
    {                                                                           \
        _Pragma("unroll")                                                       \
        for (int j = 0; j < 4; j++)                                             \
            dst[j] = __floats2half2_rn(v[8*(half) + 2*j]     * (wgt),           \
                                       v[8*(half) + 2*j + 1] * (wgt));          \
    }

    if (j0) {
        __half2 a[4], c[4];
        if (i0) { PACK4(a, w00, 0); red_v4h2(l00, a[0], a[1], a[2], a[3]); }
        if (i1) { PACK4(c, w10, 0); red_v4h2(l10, c[0], c[1], c[2], c[3]); }
        if (i0) { PACK4(a, w00, 1); red_v4h2(h00, a[0], a[1], a[2], a[3]); }
        if (i1) { PACK4(c, w10, 1); red_v4h2(h10, c[0], c[1], c[2], c[3]); }
    }
    if (j1) {
        __half2 a[4], c[4];
        if (i0) { PACK4(a, w01, 0); red_v4h2(l00 + 4, a[0], a[1], a[2], a[3]); }
        if (i1) { PACK4(c, w11, 0); red_v4h2(l10 + 4, c[0], c[1], c[2], c[3]); }
        if (i0) { PACK4(a, w01, 1); red_v4h2(h00 + 4, a[0], a[1], a[2], a[3]); }
        if (i1) { PACK4(c, w11, 1); red_v4h2(h10 + 4, c[0], c[1], c[2], c[3]); }
    }
#undef PACK4
}

// ---------------------------------------------------------------------------
// Role: zero one 4-batch group of scratch (both planes, 32 MiB).
// 1024 blocks x 256 threads x 4 uint4 x 2 planes. pix_base = 0 or HALF_PIX.
// ---------------------------------------------------------------------------
__device__ __forceinline__ void zero_role(int rb, int rt, int pix_base) {
    uint4* u = (uint4*)g_scratch;
    const uint4 z = make_uint4(0u, 0u, 0u, 0u);
    int tid = rb * 256 + rt;                    // 0 .. 262143
#pragma unroll
    for (int k = 0; k < 4; k++) {
        int off = tid + k * 262144;             // covers [0, HALF_PIX)
        u[pix_base + off]        = z;           // LO plane
        u[NPIX + pix_base + off] = z;           // HI plane
    }
}

// ---------------------------------------------------------------------------
// Role: transpose one 512-pixel tile (256 threads; R13 config, 29.9us rate).
// tb in [0, 2048) per 4-batch group; b_base = 0 or 4.
// ---------------------------------------------------------------------------
__device__ __forceinline__ void transpose_role(int tb, int t, int b_base,
                                               float* __restrict__ out) {
    __shared__ __half2 sm[8][512];   // 16 KiB (allocated kernel-wide; 8x16KB
                                     // = 128KB/SM, under the 228KB carveout)

    const __half2* s = (const __half2*)g_scratch;
    int b    = b_base + (tb >> 9);   // 512 tiles per batch
    int base = (tb & 511) * 512;     // pixel base within batch

#pragma unroll
    for (int q = 0; q < 2; q++) {
        int p = t + 256 * q;
        size_t gp = (size_t)b * HW + base + p;
        uint4 a  = __ldcs((const uint4*)(s + gp * 4));               // ch 0..7
        uint4 bq = __ldcs((const uint4*)(s + HI_OFF_H2 + gp * 4));   // ch 8..15
        sm[0][p] = *(__half2*)&a.x;  sm[1][p] = *(__half2*)&a.y;
        sm[2][p] = *(__half2*)&a.z;  sm[3][p] = *(__half2*)&a.w;
        sm[4][p] = *(__half2*)&bq.x; sm[5][p] = *(__half2*)&bq.y;
        sm[6][p] = *(__half2*)&bq.z; sm[7][p] = *(__half2*)&bq.w;
    }
    __syncthreads();

    float* ob = out + (size_t)b * CHW + base;
    int sub = t >> 7;                // 0: channel pairs 0..3, 1: pairs 4..7
    int tt  = t & 127;

#pragma unroll
    for (int r2 = 0; r2 < 4; r2++) {
        int r = sub * 4 + r2;
        uint4 raw = *(const uint4*)&sm[r][4 * tt];
        float2 f0 = __half22float2(*(__half2*)&raw.x);
        float2 f1 = __half22float2(*(__half2*)&raw.y);
        float2 f2 = __half22float2(*(__half2*)&raw.z);
        float2 f3 = __half22float2(*(__half2*)&raw.w);
        float4 ve = make_float4(f0.x, f1.x, f2.x, f3.x);  // channel 2r
        float4 vo = make_float4(f0.y, f1.y, f2.y, f3.y);  // channel 2r+1
        __stcs((float4*)(ob + (size_t)(2*r)     * HW) + tt, ve);
        __stcs((float4*)(ob + (size_t)(2*r + 1) * HW) + tt, vo);
    }
}

// ---------------------------------------------------------------------------
// K1: splat(batches 0-3)  ||  zero(scratch batches 4-7).   Disjoint data.
// K2: splat(batches 4-7)  ||  transpose(batches 0-3).      Disjoint data.
// K3: transpose(batches 4-7) || zero(scratch 0-3, for next launch).
// No cross-block waiting anywhere; kernel boundaries provide all ordering.
// Splat blocks take low bids -> dispatched first; DRAM-role blocks backfill.
// ---------------------------------------------------------------------------
__global__ __launch_bounds__(256, 8)
void k1(const float* __restrict__ x, const float2* __restrict__ grid) {
    int bid = blockIdx.x;
    if (bid < 4096) splat_pixel(x, grid, bid * 256 + threadIdx.x);
    else            zero_role(bid - 4096, threadIdx.x, HALF_PIX);
}

__global__ __launch_bounds__(256, 8)
void k2(const float* __restrict__ x, const float2* __restrict__ grid,
        float* __restrict__ out) {
    int bid = blockIdx.x;
    if (bid < 4096) splat_pixel(x, grid, HALF_PIX + bid * 256 + threadIdx.x);
    else            transpose_role(bid - 4096, threadIdx.x, 0, out);
}

__global__ __launch_bounds__(256, 8)
void k3(float* __restrict__ out) {
    int bid = blockIdx.x;
    if (bid < 2048) transpose_role(bid, threadIdx.x, 4, out);
    else            zero_role(bid - 2048, threadIdx.x, 0);
}

extern "C" void kernel_launch(void* const* d_in, const int* in_sizes, int n_in,
                              void* d_out, int out_size) {
    const float*  x    = (const float*)d_in[0];
    const float2* grid = (const float2*)d_in[1];
    float*        out  = (float*)d_out;

    k1<<<4096 + 1024, 256>>>(x, grid);        // splat 0-3  + zero 4-7
    k2<<<4096 + 2048, 256>>>(x, grid, out);   // splat 4-7  + transpose 0-3
    k3<<<2048 + 1024, 256>>>(out);            // transpose 4-7 + zero 0-3
}